// round 1
// baseline (speedup 1.0000x reference)
#include <cuda_runtime.h>
#include <math.h>

#define N 1024
#define BATCH 32
#define NMAT 33          // 32 batch Laplacians + L0
#define EPSF 1e-7f
#define NSINK 40

// ---------------- static device scratch (sanctioned by harness rules) -----
static __device__ float g_V[N * 4];
static __device__ float g_Ws[(size_t)N * N];
static __device__ float g_WsRow[N];
static __device__ float g_PrInv[BATCH * N];
static __device__ float g_col0[BATCH * N];        // WP[b][i][0] (col-0 mass for row sums)
static __device__ float g_LU[(size_t)NMAT * N * N];
static __device__ float g_invd[NMAT * 64];
static __device__ float g_y[BATCH];
static __device__ float g_ld[NMAT];

// ---------------- prep kernels --------------------------------------------

// V = softmax(V_compress, axis=1), rows of length 4
__global__ void k_vsoftmax(const float* __restrict__ Vc) {
    int i = blockIdx.x * 256 + threadIdx.x;
    if (i >= N) return;
    float4 v = reinterpret_cast<const float4*>(Vc)[i];
    float m = fmaxf(fmaxf(v.x, v.y), fmaxf(v.z, v.w));
    float a = __expf(v.x - m), b = __expf(v.y - m), c = __expf(v.z - m), d = __expf(v.w - m);
    float s = a + b + c + d;
    float r = 1.0f / s;
    float4 o; o.x = a * r; o.y = b * r; o.z = c * r; o.w = d * r;
    reinterpret_cast<float4*>(g_V)[i] = o;
}

// Pr[b,i] = V[i, x[b,i]]; store 1/Pr; y[b] = sum_i log(Pr + 1e-7)
__global__ void k_pr(const int* __restrict__ x) {
    int b = blockIdx.x;
    int i = threadIdx.x;                 // 1024 threads
    int xi = x[b * N + i];
    float pr = g_V[i * 4 + xi];
    g_PrInv[b * N + i] = 1.0f / pr;
    __shared__ float sm[N];
    sm[i] = logf(pr + 1e-7f);
    __syncthreads();
    for (int st = 512; st > 0; st >>= 1) {
        if (i < st) sm[i] += sm[i + st];
        __syncthreads();
    }
    if (i == 0) g_y[b] = sm[0];
}

// Ws = tril(sigmoid(W),-1) + its transpose
__global__ void k_ws(const float* __restrict__ W) {
    int j = blockIdx.x * 256 + threadIdx.x;
    int i = blockIdx.y;
    float v;
    if (i == j) v = 0.0f;
    else {
        float w = (i > j) ? W[(size_t)i * N + j] : W[(size_t)j * N + i];
        v = 1.0f / (1.0f + __expf(-w));
    }
    g_Ws[(size_t)i * N + j] = v;
}

__global__ void k_wsrow() {
    int i = blockIdx.x;
    __shared__ float sm[256];
    float s = 0.0f;
    for (int j = threadIdx.x; j < N; j += 256) s += g_Ws[(size_t)i * N + j];
    sm[threadIdx.x] = s;
    __syncthreads();
    for (int st = 128; st > 0; st >>= 1) {
        if (threadIdx.x < st) sm[threadIdx.x] += sm[threadIdx.x + st];
        __syncthreads();
    }
    if (threadIdx.x == 0) g_WsRow[i] = sm[0];
}

// L0[1:,1:] + 1e-7 into slot 32, padded with identity at row/col 1023
__global__ void k_l0() {
    int q = blockIdx.x * 256 + threadIdx.x;
    int p = blockIdx.y;
    float v;
    if (p == 1023 || q == 1023) v = (p == q) ? 1.0f : 0.0f;
    else {
        int i = p + 1, j = q + 1;
        v = ((p == q) ? g_WsRow[i] : 0.0f) - g_Ws[(size_t)i * N + j] + 1e-7f;
    }
    g_LU[(size_t)32 * N * N + (size_t)p * N + q] = v;
}

// identity padding row 1023 for the 32 batch matrices
__global__ void k_pad() {
    int q = blockIdx.x * 256 + threadIdx.x;
    int b = blockIdx.y;
    g_LU[(size_t)b * N * N + (size_t)1023 * N + q] = (q == 1023) ? 1.0f : 0.0f;
}

// ---------------- Sinkhorn + scatter of -WP --------------------------------
// thread (i,j), i in 1..1023 (row 0 of L is discarded), j in 0..1023
__global__ void k_sink(const int* __restrict__ x, const float* __restrict__ Ec) {
    int tid = threadIdx.x;                     // 128
    int j = blockIdx.x * 128 + tid;
    int i = blockIdx.y + 1;

    __shared__ float se[128 * 17];
    __shared__ int   sxi[BATCH];
    __shared__ float spi[BATCH];
    if (tid < BATCH) {
        sxi[tid] = x[tid * N + i];
        spi[tid] = g_PrInv[tid * N + i];
    }

    float e[16];
    if (i != j) {
        const float4* p = reinterpret_cast<const float4*>(Ec) + (size_t)(i * N + j) * 4;
        float4 q0 = p[0], q1 = p[1], q2 = p[2], q3 = p[3];
        e[0] = __expf(q0.x); e[1] = __expf(q0.y); e[2] = __expf(q0.z); e[3] = __expf(q0.w);
        e[4] = __expf(q1.x); e[5] = __expf(q1.y); e[6] = __expf(q1.z); e[7] = __expf(q1.w);
        e[8] = __expf(q2.x); e[9] = __expf(q2.y); e[10] = __expf(q2.z); e[11] = __expf(q2.w);
        e[12] = __expf(q3.x); e[13] = __expf(q3.y); e[14] = __expf(q3.z); e[15] = __expf(q3.w);
        float s = 0.0f;
        #pragma unroll
        for (int t = 0; t < 16; t++) s += e[t];
        float r0 = __fdividef(1.0f, s);
        #pragma unroll
        for (int t = 0; t < 16; t++) e[t] *= r0;

        float4 vi4 = reinterpret_cast<const float4*>(g_V)[i];
        float4 vj4 = reinterpret_cast<const float4*>(g_V)[j];
        float Vi[4] = {vi4.x, vi4.y, vi4.z, vi4.w};
        float Vj[4] = {vj4.x, vj4.y, vj4.z, vj4.w};

        #pragma unroll 1
        for (int it = 0; it < NSINK; ++it) {
            #pragma unroll
            for (int a = 0; a < 4; a++) {
                float rs = e[4*a] + e[4*a+1] + e[4*a+2] + e[4*a+3];
                float rr = __fdividef(Vi[a], rs + EPSF);
                e[4*a] *= rr; e[4*a+1] *= rr; e[4*a+2] *= rr; e[4*a+3] *= rr;
            }
            #pragma unroll
            for (int b = 0; b < 4; b++) {
                float cs = e[b] + e[b+4] + e[b+8] + e[b+12];
                float cc = __fdividef(Vj[b], cs + EPSF);
                e[b] *= cc; e[b+4] *= cc; e[b+8] *= cc; e[b+12] *= cc;
            }
            float t = 0.0f;
            #pragma unroll
            for (int u = 0; u < 16; u++) t += e[u];
            float tr = __fdividef(1.0f, t + EPSF);
            #pragma unroll
            for (int u = 0; u < 16; u++) e[u] *= tr;
        }
        #pragma unroll
        for (int t = 0; t < 16; t++) e[t] = fminf(fmaxf(e[t], 0.0f), 1.0f);
    } else {
        #pragma unroll
        for (int t = 0; t < 16; t++) e[t] = 0.0f;
    }

    #pragma unroll
    for (int t = 0; t < 16; t++) se[tid * 17 + t] = e[t];
    __syncthreads();

    float wij = g_Ws[(size_t)i * N + j];
    #pragma unroll 1
    for (int b = 0; b < BATCH; b++) {
        int a = sxi[b];
        int c = x[b * N + j];
        float val = wij * se[tid * 17 + (a * 4 + c)] * spi[b] * g_PrInv[b * N + j];
        if (j == 0) g_col0[b * N + i] = val;
        else g_LU[(size_t)b * N * N + (size_t)(i - 1) * N + (j - 1)] = -val;
    }
}

// finalize rows: diag = rowsum(WP), add 1e-7, zero padding col
__global__ void k_fin() {
    int b = blockIdx.y;
    int p = blockIdx.x;                   // 0..1022
    float* row = g_LU + (size_t)b * N * N + (size_t)p * N;
    __shared__ float sm[256];
    float s = 0.0f;
    for (int q = threadIdx.x; q < 1023; q += 256) s -= row[q];   // sum of WP
    sm[threadIdx.x] = s;
    __syncthreads();
    for (int st = 128; st > 0; st >>= 1) {
        if (threadIdx.x < st) sm[threadIdx.x] += sm[threadIdx.x + st];
        __syncthreads();
    }
    float diag = sm[0] + g_col0[b * N + (p + 1)];
    __syncthreads();
    for (int q = threadIdx.x; q < 1023; q += 256) {
        float v = row[q] + 1e-7f;
        if (q == p) v = diag + 1e-7f;
        row[q] = v;
    }
    if (threadIdx.x == 0) row[1023] = 0.0f;
}

// ---------------- blocked unpivoted LU (nb = 64) ---------------------------

__global__ void k_panelLU(int k) {
    int mat = blockIdx.x;
    float* A = g_LU + (size_t)mat * N * N;
    __shared__ float sA[64][65];
    __shared__ float sInv[64];
    int tid = threadIdx.x;  // 256
    for (int t = tid; t < 64 * 64; t += 256) {
        int r = t >> 6, c = t & 63;
        sA[r][c] = A[(size_t)(k + r) * N + k + c];
    }
    __syncthreads();
    for (int c = 0; c < 64; c++) {
        if (tid == 0) sInv[c] = 1.0f / sA[c][c];
        __syncthreads();
        float inv = sInv[c];
        if (tid > c && tid < 64) sA[tid][c] *= inv;
        __syncthreads();
        int w = 63 - c;
        for (int t = tid; t < w * w; t += 256) {
            int r = c + 1 + t / w, cc = c + 1 + t % w;
            sA[r][cc] -= sA[r][c] * sA[c][cc];
        }
        __syncthreads();
    }
    for (int t = tid; t < 64 * 64; t += 256) {
        int r = t >> 6, c = t & 63;
        A[(size_t)(k + r) * N + k + c] = sA[r][c];
    }
    if (tid < 64) g_invd[mat * 64 + tid] = sInv[tid];
}

// L21 = A21 * U11^{-1}, one row per thread
__global__ void k_l21(int k) {
    int mat = blockIdx.y;
    float* A = g_LU + (size_t)mat * N * N;
    int tid = threadIdx.x;  // 64
    __shared__ float sU[64][65];
    __shared__ float sInv[64];
    for (int t = tid; t < 64 * 64; t += 64) {
        int r = t >> 6, c = t & 63;
        sU[r][c] = A[(size_t)(k + r) * N + k + c];
    }
    sInv[tid] = g_invd[mat * 64 + tid];
    __syncthreads();
    int g = k + 64 + blockIdx.x * 64 + tid;
    float* rowp = A + (size_t)g * N + k;
    float a[64];
    #pragma unroll
    for (int c = 0; c < 16; c++) {
        float4 v = reinterpret_cast<const float4*>(rowp)[c];
        a[4 * c] = v.x; a[4 * c + 1] = v.y; a[4 * c + 2] = v.z; a[4 * c + 3] = v.w;
    }
    #pragma unroll
    for (int d = 0; d < 64; d++) {
        a[d] *= sInv[d];
        #pragma unroll
        for (int c = d + 1; c < 64; c++) a[c] -= a[d] * sU[d][c];
    }
    #pragma unroll
    for (int c = 0; c < 16; c++) {
        float4 v; v.x = a[4 * c]; v.y = a[4 * c + 1]; v.z = a[4 * c + 2]; v.w = a[4 * c + 3];
        reinterpret_cast<float4*>(rowp)[c] = v;
    }
}

// U12 = L11^{-1} * A12, one column per thread (coalesced)
__global__ void k_u12(int k) {
    int mat = blockIdx.y;
    float* A = g_LU + (size_t)mat * N * N;
    int tid = threadIdx.x;  // 64
    __shared__ float sL[64][65];
    for (int t = tid; t < 64 * 64; t += 64) {
        int r = t >> 6, c = t & 63;
        sL[r][c] = A[(size_t)(k + r) * N + k + c];
    }
    __syncthreads();
    int g = k + 64 + blockIdx.x * 64 + tid;
    float a[64];
    #pragma unroll
    for (int d = 0; d < 64; d++) a[d] = A[(size_t)(k + d) * N + g];
    #pragma unroll
    for (int d = 0; d < 64; d++) {
        #pragma unroll
        for (int r = d + 1; r < 64; r++) a[r] -= sL[r][d] * a[d];
    }
    #pragma unroll
    for (int d = 0; d < 64; d++) A[(size_t)(k + d) * N + g] = a[d];
}

// trailing update: C -= L21 * U12; 64x64 tile per block, 4x4 per thread
__global__ void k_gemm(int k) {
    int mat = blockIdx.z;
    float* M = g_LU + (size_t)mat * N * N;
    int row0 = k + 64 + blockIdx.y * 64;
    int col0 = k + 64 + blockIdx.x * 64;
    __shared__ float sA[16][68];   // transposed A chunk
    __shared__ float sB[16][64];
    int tid = threadIdx.x;         // 256
    int tx = tid & 15, ty = tid >> 4;
    float acc[4][4];
    #pragma unroll
    for (int y = 0; y < 4; y++)
        #pragma unroll
        for (int xq = 0; xq < 4; xq++) acc[y][xq] = 0.0f;

    int ar = tid >> 2;
    int acx = (tid & 3) * 4;
    int br = tid >> 4;
    int bc = (tid & 15) * 4;

    for (int kk = 0; kk < 64; kk += 16) {
        float4 av = *reinterpret_cast<const float4*>(&M[(size_t)(row0 + ar) * N + k + kk + acx]);
        float4 bv = *reinterpret_cast<const float4*>(&M[(size_t)(k + kk + br) * N + col0 + bc]);
        __syncthreads();
        sA[acx + 0][ar] = av.x; sA[acx + 1][ar] = av.y;
        sA[acx + 2][ar] = av.z; sA[acx + 3][ar] = av.w;
        *reinterpret_cast<float4*>(&sB[br][bc]) = bv;
        __syncthreads();
        #pragma unroll
        for (int t = 0; t < 16; t++) {
            float4 a4 = *reinterpret_cast<const float4*>(&sA[t][ty * 4]);
            float4 b4 = *reinterpret_cast<const float4*>(&sB[t][tx * 4]);
            acc[0][0] += a4.x * b4.x; acc[0][1] += a4.x * b4.y; acc[0][2] += a4.x * b4.z; acc[0][3] += a4.x * b4.w;
            acc[1][0] += a4.y * b4.x; acc[1][1] += a4.y * b4.y; acc[1][2] += a4.y * b4.z; acc[1][3] += a4.y * b4.w;
            acc[2][0] += a4.z * b4.x; acc[2][1] += a4.z * b4.y; acc[2][2] += a4.z * b4.z; acc[2][3] += a4.z * b4.w;
            acc[3][0] += a4.w * b4.x; acc[3][1] += a4.w * b4.y; acc[3][2] += a4.w * b4.z; acc[3][3] += a4.w * b4.w;
        }
    }
    #pragma unroll
    for (int y = 0; y < 4; y++) {
        float4* cp = reinterpret_cast<float4*>(&M[(size_t)(row0 + ty * 4 + y) * N + col0 + tx * 4]);
        float4 cv = *cp;
        cv.x -= acc[y][0]; cv.y -= acc[y][1]; cv.z -= acc[y][2]; cv.w -= acc[y][3];
        *cp = cv;
    }
}

// ---------------- epilogue -------------------------------------------------

__global__ void k_logdet() {
    int mat = blockIdx.x;
    __shared__ float sm[256];
    float s = 0.0f;
    for (int d = threadIdx.x; d < 1023; d += 256)
        s += logf(fabsf(g_LU[(size_t)mat * N * N + (size_t)d * N + d]));
    sm[threadIdx.x] = s;
    __syncthreads();
    for (int st = 128; st > 0; st >>= 1) {
        if (threadIdx.x < st) sm[threadIdx.x] += sm[threadIdx.x + st];
        __syncthreads();
    }
    if (threadIdx.x == 0) g_ld[mat] = sm[0];
}

__global__ void k_out(float* __restrict__ out) {
    int b = threadIdx.x;
    if (b < BATCH) out[b] = g_y[b] + g_ld[b] - g_ld[32];
}

// ---------------- launch ----------------------------------------------------
extern "C" void kernel_launch(void* const* d_in, const int* in_sizes, int n_in,
                              void* d_out, int out_size) {
    const int*   x  = (const int*)d_in[0];
    const float* W  = (const float*)d_in[1];
    const float* Vc = (const float*)d_in[2];
    const float* Ec = (const float*)d_in[3];
    float* out = (float*)d_out;
    (void)in_sizes; (void)n_in; (void)out_size;

    k_vsoftmax<<<4, 256>>>(Vc);
    k_pr<<<BATCH, 1024>>>(x);
    k_ws<<<dim3(4, N), 256>>>(W);
    k_wsrow<<<N, 256>>>();
    k_l0<<<dim3(4, N), 256>>>();
    k_pad<<<dim3(4, BATCH), 256>>>();
    k_sink<<<dim3(8, N - 1), 128>>>(x, Ec);
    k_fin<<<dim3(N - 1, BATCH), 256>>>();

    for (int s = 0; s < 16; s++) {
        int k = s * 64;
        k_panelLU<<<NMAT, 256>>>(k);
        int m2 = N - k - 64;
        if (m2 > 0) {
            k_l21<<<dim3(m2 / 64, NMAT), 64>>>(k);
            k_u12<<<dim3(m2 / 64, NMAT), 64>>>(k);
            k_gemm<<<dim3(m2 / 64, m2 / 64, NMAT), 256>>>(k);
        }
    }

    k_logdet<<<NMAT, 256>>>();
    k_out<<<1, 32>>>(out);
}

// round 2
// speedup vs baseline: 1.0004x; 1.0004x over previous
#include <cuda_runtime.h>
#include <math.h>

#define N 1024
#define BATCH 32
#define NMAT 33          // 32 batch Laplacians + L0
#define EPSF 1e-7f
#define NSINK 40

// ---------------- static device scratch ------------------------------------
static __device__ float g_V[N * 4];
static __device__ float g_Ws[(size_t)N * N];
static __device__ float g_WsRow[N];
static __device__ float g_PrInv[BATCH * N];
static __device__ float g_col0[BATCH * N];        // WP[b][i][0]
static __device__ float g_LU[(size_t)NMAT * N * N];
static __device__ float g_invd[NMAT * 64];
static __device__ float g_y[BATCH];
static __device__ float g_ld[NMAT];

// ---------------- prep kernels ----------------------------------------------

__global__ void k_vsoftmax(const float* __restrict__ Vc) {
    int i = blockIdx.x * 256 + threadIdx.x;
    if (i >= N) return;
    float4 v = reinterpret_cast<const float4*>(Vc)[i];
    float m = fmaxf(fmaxf(v.x, v.y), fmaxf(v.z, v.w));
    float a = __expf(v.x - m), b = __expf(v.y - m), c = __expf(v.z - m), d = __expf(v.w - m);
    float r = 1.0f / (a + b + c + d);
    float4 o; o.x = a * r; o.y = b * r; o.z = c * r; o.w = d * r;
    reinterpret_cast<float4*>(g_V)[i] = o;
}

__global__ void k_pr(const int* __restrict__ x) {
    int b = blockIdx.x;
    int i = threadIdx.x;                 // 1024 threads
    int xi = x[b * N + i];
    float pr = g_V[i * 4 + xi];
    g_PrInv[b * N + i] = 1.0f / pr;
    __shared__ float sm[N];
    sm[i] = logf(pr + 1e-7f);
    __syncthreads();
    for (int st = 512; st > 0; st >>= 1) {
        if (i < st) sm[i] += sm[i + st];
        __syncthreads();
    }
    if (i == 0) g_y[b] = sm[0];
}

// Ws row + rowsum fused: one block per row i
__global__ void k_ws(const float* __restrict__ W) {
    int i = blockIdx.x;
    __shared__ float sm[256];
    float s = 0.0f;
    for (int j = threadIdx.x; j < N; j += 256) {
        float v;
        if (i == j) v = 0.0f;
        else {
            float w = (i > j) ? W[(size_t)i * N + j] : W[(size_t)j * N + i];
            v = 1.0f / (1.0f + __expf(-w));
        }
        g_Ws[(size_t)i * N + j] = v;
        s += v;
    }
    sm[threadIdx.x] = s;
    __syncthreads();
    for (int st = 128; st > 0; st >>= 1) {
        if (threadIdx.x < st) sm[threadIdx.x] += sm[threadIdx.x + st];
        __syncthreads();
    }
    if (threadIdx.x == 0) g_WsRow[i] = sm[0];
}

// L0[1:,1:] + 1e-7 into slot 32, identity-padded at row/col 1023
__global__ void k_l0() {
    int q = blockIdx.x * 256 + threadIdx.x;
    int p = blockIdx.y;
    float v;
    if (p == 1023 || q == 1023) v = (p == q) ? 1.0f : 0.0f;
    else {
        int i = p + 1, j = q + 1;
        v = ((p == q) ? g_WsRow[i] : 0.0f) - g_Ws[(size_t)i * N + j] + 1e-7f;
    }
    g_LU[(size_t)32 * N * N + (size_t)p * N + q] = v;
}

// ---------------- Sinkhorn + scatter of (1e-7 - WP) -------------------------
__global__ void k_sink(const int* __restrict__ x, const float* __restrict__ Ec) {
    int tid = threadIdx.x;                     // 128
    int j = blockIdx.x * 128 + tid;
    int i = blockIdx.y + 1;

    __shared__ float se[128 * 17];
    __shared__ int   sxi[BATCH];
    __shared__ float spi[BATCH];
    if (tid < BATCH) {
        sxi[tid] = x[tid * N + i];
        spi[tid] = g_PrInv[tid * N + i];
    }

    float e[16];
    if (i != j) {
        const float4* p = reinterpret_cast<const float4*>(Ec) + (size_t)(i * N + j) * 4;
        float4 q0 = p[0], q1 = p[1], q2 = p[2], q3 = p[3];
        e[0] = __expf(q0.x); e[1] = __expf(q0.y); e[2] = __expf(q0.z); e[3] = __expf(q0.w);
        e[4] = __expf(q1.x); e[5] = __expf(q1.y); e[6] = __expf(q1.z); e[7] = __expf(q1.w);
        e[8] = __expf(q2.x); e[9] = __expf(q2.y); e[10] = __expf(q2.z); e[11] = __expf(q2.w);
        e[12] = __expf(q3.x); e[13] = __expf(q3.y); e[14] = __expf(q3.z); e[15] = __expf(q3.w);
        float s = 0.0f;
        #pragma unroll
        for (int t = 0; t < 16; t++) s += e[t];
        float r0 = __fdividef(1.0f, s);
        #pragma unroll
        for (int t = 0; t < 16; t++) e[t] *= r0;

        float4 vi4 = reinterpret_cast<const float4*>(g_V)[i];
        float4 vj4 = reinterpret_cast<const float4*>(g_V)[j];
        float Vi[4] = {vi4.x, vi4.y, vi4.z, vi4.w};
        float Vj[4] = {vj4.x, vj4.y, vj4.z, vj4.w};

        // total-normalization per iter dropped: after the row step total mass
        // == sum(Vi) == 1, so the reference's global divide is by 1+O(eps);
        // relative perturbation O(eps^2) ~ 1e-14. One normalize at the end.
        #pragma unroll 1
        for (int it = 0; it < NSINK; ++it) {
            #pragma unroll
            for (int a = 0; a < 4; a++) {
                float rs = e[4*a] + e[4*a+1] + e[4*a+2] + e[4*a+3];
                float rr = __fdividef(Vi[a], rs + EPSF);
                e[4*a] *= rr; e[4*a+1] *= rr; e[4*a+2] *= rr; e[4*a+3] *= rr;
            }
            #pragma unroll
            for (int b = 0; b < 4; b++) {
                float cs = e[b] + e[b+4] + e[b+8] + e[b+12];
                float cc = __fdividef(Vj[b], cs + EPSF);
                e[b] *= cc; e[b+4] *= cc; e[b+8] *= cc; e[b+12] *= cc;
            }
        }
        float t = 0.0f;
        #pragma unroll
        for (int u = 0; u < 16; u++) t += e[u];
        float tr = __fdividef(1.0f, t + EPSF);
        #pragma unroll
        for (int u = 0; u < 16; u++)
            e[u] = fminf(fmaxf(e[u] * tr, 0.0f), 1.0f);
    } else {
        #pragma unroll
        for (int t = 0; t < 16; t++) e[t] = 0.0f;
    }

    #pragma unroll
    for (int t = 0; t < 16; t++) se[tid * 17 + t] = e[t];
    __syncthreads();

    float wij = g_Ws[(size_t)i * N + j];
    #pragma unroll 1
    for (int b = 0; b < BATCH; b++) {
        int a = sxi[b];
        int c = x[b * N + j];
        float val = wij * se[tid * 17 + (a * 4 + c)] * spi[b] * g_PrInv[b * N + j];
        if (j == 0) g_col0[b * N + i] = val;
        else g_LU[(size_t)b * N * N + (size_t)(i - 1) * N + (j - 1)] = 1e-7f - val;
    }
}

// finalize: diag = rowsum(WP) + 1e-7, pad col/row. Read-mostly now.
__global__ void k_fin() {
    int b = blockIdx.y;
    int p = blockIdx.x;                   // 0..1023
    float* row = g_LU + (size_t)b * N * N + (size_t)p * N;
    if (p == 1023) {
        for (int q = threadIdx.x; q < N; q += 256) row[q] = (q == 1023) ? 1.0f : 0.0f;
        return;
    }
    __shared__ float sm[256];
    float s = 0.0f;
    for (int q = threadIdx.x; q < 1023; q += 256) s += row[q];   // sum of (1e-7 - WP)
    sm[threadIdx.x] = s;
    __syncthreads();
    for (int st = 128; st > 0; st >>= 1) {
        if (threadIdx.x < st) sm[threadIdx.x] += sm[threadIdx.x + st];
        __syncthreads();
    }
    if (threadIdx.x == 0) {
        float wpsum = 1023.0f * 1e-7f - sm[0] + g_col0[b * N + (p + 1)];
        row[p] = wpsum + 1e-7f;
        row[1023] = 0.0f;
    }
}

// ---------------- blocked unpivoted LU (nb = 64) ----------------------------

__global__ void k_panelLU(int k) {
    int mat = blockIdx.x;
    float* A = g_LU + (size_t)mat * N * N;
    __shared__ float sA[64][65];
    __shared__ float sInv[64];
    int tid = threadIdx.x;  // 256
    for (int t = tid; t < 64 * 64; t += 256) {
        int r = t >> 6, c = t & 63;
        sA[r][c] = A[(size_t)(k + r) * N + k + c];
    }
    __syncthreads();
    for (int c = 0; c < 64; c++) {
        if (tid == 0) sInv[c] = 1.0f / sA[c][c];
        __syncthreads();
        float inv = sInv[c];
        if (tid > c && tid < 64) sA[tid][c] *= inv;
        __syncthreads();
        int w = 63 - c;
        for (int t = tid; t < w * w; t += 256) {
            int r = c + 1 + t / w, cc = c + 1 + t % w;
            sA[r][cc] -= sA[r][c] * sA[c][cc];
        }
        __syncthreads();
    }
    for (int t = tid; t < 64 * 64; t += 256) {
        int r = t >> 6, c = t & 63;
        A[(size_t)(k + r) * N + k + c] = sA[r][c];
    }
    if (tid < 64) g_invd[mat * 64 + tid] = sInv[tid];
}

// fused TRSMs: z==0 -> L21 = A21*U11^{-1} (row/thread); z==1 -> U12 = L11^{-1}*A12
__global__ void k_trsm(int k) {
    int mat = blockIdx.y;
    float* A = g_LU + (size_t)mat * N * N;
    int tid = threadIdx.x;  // 64
    __shared__ float sU[64][65];
    __shared__ float sInv[64];
    for (int t = tid; t < 64 * 64; t += 64) {
        int r = t >> 6, c = t & 63;
        sU[r][c] = A[(size_t)(k + r) * N + k + c];
    }
    if (blockIdx.z == 0) sInv[tid] = g_invd[mat * 64 + tid];
    __syncthreads();
    int g = k + 64 + blockIdx.x * 64 + tid;
    if (blockIdx.z == 0) {
        float* rowp = A + (size_t)g * N + k;
        float a[64];
        #pragma unroll
        for (int c = 0; c < 16; c++) {
            float4 v = reinterpret_cast<const float4*>(rowp)[c];
            a[4 * c] = v.x; a[4 * c + 1] = v.y; a[4 * c + 2] = v.z; a[4 * c + 3] = v.w;
        }
        #pragma unroll
        for (int d = 0; d < 64; d++) {
            a[d] *= sInv[d];
            #pragma unroll
            for (int c = d + 1; c < 64; c++) a[c] -= a[d] * sU[d][c];
        }
        #pragma unroll
        for (int c = 0; c < 16; c++) {
            float4 v; v.x = a[4 * c]; v.y = a[4 * c + 1]; v.z = a[4 * c + 2]; v.w = a[4 * c + 3];
            reinterpret_cast<float4*>(rowp)[c] = v;
        }
    } else {
        float a[64];
        #pragma unroll
        for (int d = 0; d < 64; d++) a[d] = A[(size_t)(k + d) * N + g];
        #pragma unroll
        for (int d = 0; d < 64; d++) {
            #pragma unroll
            for (int r = d + 1; r < 64; r++) a[r] -= sU[r][d] * a[d];
        }
        #pragma unroll
        for (int d = 0; d < 64; d++) A[(size_t)(k + d) * N + g] = a[d];
    }
}

// trailing update: C -= L21 * U12; 128x64 tile per block, 8x4 per thread
__global__ void k_gemm(int k) {
    int mat = blockIdx.z;
    float* M = g_LU + (size_t)mat * N * N;
    int row0 = k + 64 + blockIdx.y * 128;
    int col0 = k + 64 + blockIdx.x * 64;
    __shared__ float sA[16][132];   // sA[kk][row], transposed A chunk
    __shared__ float sB[16][64];
    int tid = threadIdx.x;          // 256
    int tx = tid & 15, ty = tid >> 4;

    float acc[8][4];
    #pragma unroll
    for (int y = 0; y < 8; y++)
        #pragma unroll
        for (int xq = 0; xq < 4; xq++) acc[y][xq] = 0.0f;

    int ar = tid >> 2;              // 0..63 (handles rows ar and ar+64)
    int ac = (tid & 3) * 4;
    int br = tid >> 4;
    int bc = (tid & 15) * 4;

    for (int kk = 0; kk < 64; kk += 16) {
        int r1 = row0 + ar;
        int r2 = r1 + 64;
        float4 a1 = *reinterpret_cast<const float4*>(&M[(size_t)min(r1, 1023) * N + k + kk + ac]);
        float4 a2 = *reinterpret_cast<const float4*>(&M[(size_t)min(r2, 1023) * N + k + kk + ac]);
        float4 bv = *reinterpret_cast<const float4*>(&M[(size_t)(k + kk + br) * N + col0 + bc]);
        __syncthreads();
        sA[ac + 0][ar] = a1.x; sA[ac + 1][ar] = a1.y;
        sA[ac + 2][ar] = a1.z; sA[ac + 3][ar] = a1.w;
        sA[ac + 0][ar + 64] = a2.x; sA[ac + 1][ar + 64] = a2.y;
        sA[ac + 2][ar + 64] = a2.z; sA[ac + 3][ar + 64] = a2.w;
        *reinterpret_cast<float4*>(&sB[br][bc]) = bv;
        __syncthreads();
        #pragma unroll
        for (int t = 0; t < 16; t++) {
            float4 a4 = *reinterpret_cast<const float4*>(&sA[t][ty * 8]);
            float4 a4b = *reinterpret_cast<const float4*>(&sA[t][ty * 8 + 4]);
            float4 b4 = *reinterpret_cast<const float4*>(&sB[t][tx * 4]);
            acc[0][0] += a4.x * b4.x;  acc[0][1] += a4.x * b4.y;  acc[0][2] += a4.x * b4.z;  acc[0][3] += a4.x * b4.w;
            acc[1][0] += a4.y * b4.x;  acc[1][1] += a4.y * b4.y;  acc[1][2] += a4.y * b4.z;  acc[1][3] += a4.y * b4.w;
            acc[2][0] += a4.z * b4.x;  acc[2][1] += a4.z * b4.y;  acc[2][2] += a4.z * b4.z;  acc[2][3] += a4.z * b4.w;
            acc[3][0] += a4.w * b4.x;  acc[3][1] += a4.w * b4.y;  acc[3][2] += a4.w * b4.z;  acc[3][3] += a4.w * b4.w;
            acc[4][0] += a4b.x * b4.x; acc[4][1] += a4b.x * b4.y; acc[4][2] += a4b.x * b4.z; acc[4][3] += a4b.x * b4.w;
            acc[5][0] += a4b.y * b4.x; acc[5][1] += a4b.y * b4.y; acc[5][2] += a4b.y * b4.z; acc[5][3] += a4b.y * b4.w;
            acc[6][0] += a4b.z * b4.x; acc[6][1] += a4b.z * b4.y; acc[6][2] += a4b.z * b4.z; acc[6][3] += a4b.z * b4.w;
            acc[7][0] += a4b.w * b4.x; acc[7][1] += a4b.w * b4.y; acc[7][2] += a4b.w * b4.z; acc[7][3] += a4b.w * b4.w;
        }
    }
    #pragma unroll
    for (int y = 0; y < 8; y++) {
        int r = row0 + ty * 8 + y;
        if (r < 1024) {
            float4* cp = reinterpret_cast<float4*>(&M[(size_t)r * N + col0 + tx * 4]);
            float4 cv = *cp;
            cv.x -= acc[y][0]; cv.y -= acc[y][1]; cv.z -= acc[y][2]; cv.w -= acc[y][3];
            *cp = cv;
        }
    }
}

// ---------------- epilogue ---------------------------------------------------

__global__ void k_logdet() {
    int mat = blockIdx.x;
    __shared__ float sm[256];
    float s = 0.0f;
    for (int d = threadIdx.x; d < 1023; d += 256)
        s += logf(fabsf(g_LU[(size_t)mat * N * N + (size_t)d * N + d]));
    sm[threadIdx.x] = s;
    __syncthreads();
    for (int st = 128; st > 0; st >>= 1) {
        if (threadIdx.x < st) sm[threadIdx.x] += sm[threadIdx.x + st];
        __syncthreads();
    }
    if (threadIdx.x == 0) g_ld[mat] = sm[0];
}

__global__ void k_out(float* __restrict__ out) {
    int b = threadIdx.x;
    if (b < BATCH) out[b] = g_y[b] + g_ld[b] - g_ld[32];
}

// ---------------- launch ------------------------------------------------------
extern "C" void kernel_launch(void* const* d_in, const int* in_sizes, int n_in,
                              void* d_out, int out_size) {
    const int*   x  = (const int*)d_in[0];
    const float* W  = (const float*)d_in[1];
    const float* Vc = (const float*)d_in[2];
    const float* Ec = (const float*)d_in[3];
    float* out = (float*)d_out;
    (void)in_sizes; (void)n_in; (void)out_size;

    k_vsoftmax<<<4, 256>>>(Vc);
    k_pr<<<BATCH, 1024>>>(x);
    k_ws<<<N, 256>>>(W);
    k_l0<<<dim3(4, N), 256>>>();
    k_sink<<<dim3(8, N - 1), 128>>>(x, Ec);
    k_fin<<<dim3(N, BATCH), 256>>>();

    for (int s = 0; s < 16; s++) {
        int k = s * 64;
        k_panelLU<<<NMAT, 256>>>(k);
        int m2 = N - k - 64;
        if (m2 > 0) {
            k_trsm<<<dim3(m2 / 64, NMAT, 2), 64>>>(k);
            k_gemm<<<dim3(m2 / 64, (m2 + 127) / 128, NMAT), 256>>>(k);
        }
    }

    k_logdet<<<NMAT, 256>>>();
    k_out<<<1, 32>>>(out);
}

// round 3
// speedup vs baseline: 1.2650x; 1.2645x over previous
#include <cuda_runtime.h>
#include <math.h>

#define N 1024
#define BATCH 32
#define NMAT 33          // 32 batch Laplacians + L0
#define EPSF 1e-7f
#define NSINK 40

// ---------------- static device scratch ------------------------------------
static __device__ float g_V[N * 4];
static __device__ float g_Ws[(size_t)N * N];
static __device__ float g_PrInv[BATCH * N];
static __device__ float g_col0[BATCH * N];        // WP[b][i][0]
static __device__ float g_LU[(size_t)NMAT * N * N];
static __device__ float g_invd[NMAT * 64];
static __device__ float g_y[BATCH];
static __device__ float g_ld[NMAT];

// ---------------- prep kernels ----------------------------------------------

__global__ void k_vsoftmax(const float* __restrict__ Vc) {
    int i = blockIdx.x * 256 + threadIdx.x;
    if (i >= N) return;
    float4 v = reinterpret_cast<const float4*>(Vc)[i];
    float m = fmaxf(fmaxf(v.x, v.y), fmaxf(v.z, v.w));
    float a = __expf(v.x - m), b = __expf(v.y - m), c = __expf(v.z - m), d = __expf(v.w - m);
    float r = 1.0f / (a + b + c + d);
    float4 o; o.x = a * r; o.y = b * r; o.z = c * r; o.w = d * r;
    reinterpret_cast<float4*>(g_V)[i] = o;
}

__global__ void k_pr(const int* __restrict__ x) {
    int b = blockIdx.x;
    int i = threadIdx.x;                 // 1024 threads
    int xi = x[b * N + i];
    float pr = g_V[i * 4 + xi];
    g_PrInv[b * N + i] = 1.0f / pr;
    __shared__ float sm[N];
    sm[i] = logf(pr + 1e-7f);
    __syncthreads();
    for (int st = 512; st > 0; st >>= 1) {
        if (i < st) sm[i] += sm[i + st];
        __syncthreads();
    }
    if (i == 0) g_y[b] = sm[0];
}

// One block per row i: build Ws row (+rowsum) AND write the L0 row directly.
__global__ void k_ws(const float* __restrict__ W) {
    int i = blockIdx.x;
    __shared__ float sWs[N];
    __shared__ float sm[256];
    float s = 0.0f;
    for (int j = threadIdx.x; j < N; j += 256) {
        float v;
        if (i == j) v = 0.0f;
        else {
            float w = (i > j) ? W[(size_t)i * N + j] : W[(size_t)j * N + i];
            v = 1.0f / (1.0f + __expf(-w));
        }
        g_Ws[(size_t)i * N + j] = v;
        sWs[j] = v;
        s += v;
    }
    sm[threadIdx.x] = s;
    __syncthreads();
    for (int st = 128; st > 0; st >>= 1) {
        if (threadIdx.x < st) sm[threadIdx.x] += sm[threadIdx.x + st];
        __syncthreads();
    }
    float rowsum = sm[0];
    float* L0 = g_LU + (size_t)32 * N * N;
    if (i >= 1) {
        int p = i - 1;
        for (int q = threadIdx.x; q < N; q += 256) {
            float v;
            if (q == 1023) v = 0.0f;
            else v = ((q == p) ? rowsum : 0.0f) - sWs[q + 1] + 1e-7f;
            L0[(size_t)p * N + q] = v;
        }
    } else {
        // identity padding row 1023 of L0
        for (int q = threadIdx.x; q < N; q += 256)
            L0[(size_t)1023 * N + q] = (q == 1023) ? 1.0f : 0.0f;
    }
}

// ---------------- Sinkhorn + scatter of (1e-7 - WP) -------------------------
__global__ void k_sink(const int* __restrict__ x, const float* __restrict__ Ec) {
    int tid = threadIdx.x;                     // 128
    int j = blockIdx.x * 128 + tid;
    int i = blockIdx.y + 1;

    __shared__ float se[128 * 17];
    __shared__ int   sxi[BATCH];
    __shared__ float spi[BATCH];
    if (tid < BATCH) {
        sxi[tid] = x[tid * N + i];
        spi[tid] = g_PrInv[tid * N + i];
    }

    float e[16];
    if (i != j) {
        const float4* p = reinterpret_cast<const float4*>(Ec) + (size_t)(i * N + j) * 4;
        float4 q0 = p[0], q1 = p[1], q2 = p[2], q3 = p[3];
        e[0] = __expf(q0.x); e[1] = __expf(q0.y); e[2] = __expf(q0.z); e[3] = __expf(q0.w);
        e[4] = __expf(q1.x); e[5] = __expf(q1.y); e[6] = __expf(q1.z); e[7] = __expf(q1.w);
        e[8] = __expf(q2.x); e[9] = __expf(q2.y); e[10] = __expf(q2.z); e[11] = __expf(q2.w);
        e[12] = __expf(q3.x); e[13] = __expf(q3.y); e[14] = __expf(q3.z); e[15] = __expf(q3.w);
        float s = 0.0f;
        #pragma unroll
        for (int t = 0; t < 16; t++) s += e[t];
        float r0 = __fdividef(1.0f, s);
        #pragma unroll
        for (int t = 0; t < 16; t++) e[t] *= r0;

        float4 vi4 = reinterpret_cast<const float4*>(g_V)[i];
        float4 vj4 = reinterpret_cast<const float4*>(g_V)[j];
        float Vi[4] = {vi4.x, vi4.y, vi4.z, vi4.w};
        float Vj[4] = {vj4.x, vj4.y, vj4.z, vj4.w};

        #pragma unroll 1
        for (int it = 0; it < NSINK; ++it) {
            #pragma unroll
            for (int a = 0; a < 4; a++) {
                float rs = e[4*a] + e[4*a+1] + e[4*a+2] + e[4*a+3];
                float rr = __fdividef(Vi[a], rs + EPSF);
                e[4*a] *= rr; e[4*a+1] *= rr; e[4*a+2] *= rr; e[4*a+3] *= rr;
            }
            #pragma unroll
            for (int b = 0; b < 4; b++) {
                float cs = e[b] + e[b+4] + e[b+8] + e[b+12];
                float cc = __fdividef(Vj[b], cs + EPSF);
                e[b] *= cc; e[b+4] *= cc; e[b+8] *= cc; e[b+12] *= cc;
            }
        }
        float t = 0.0f;
        #pragma unroll
        for (int u = 0; u < 16; u++) t += e[u];
        float tr = __fdividef(1.0f, t + EPSF);
        #pragma unroll
        for (int u = 0; u < 16; u++)
            e[u] = fminf(fmaxf(e[u] * tr, 0.0f), 1.0f);
    } else {
        #pragma unroll
        for (int t = 0; t < 16; t++) e[t] = 0.0f;
    }

    #pragma unroll
    for (int t = 0; t < 16; t++) se[tid * 17 + t] = e[t];
    __syncthreads();

    float wij = g_Ws[(size_t)i * N + j];
    #pragma unroll 1
    for (int b = 0; b < BATCH; b++) {
        int a = sxi[b];
        int c = x[b * N + j];
        float val = wij * se[tid * 17 + (a * 4 + c)] * spi[b] * g_PrInv[b * N + j];
        if (j == 0) g_col0[b * N + i] = val;
        else g_LU[(size_t)b * N * N + (size_t)(i - 1) * N + (j - 1)] = 1e-7f - val;
    }
}

// finalize: diag = rowsum(WP) + 1e-7, pad row/col
__global__ void k_fin() {
    int b = blockIdx.y;
    int p = blockIdx.x;                   // 0..1023
    float* row = g_LU + (size_t)b * N * N + (size_t)p * N;
    if (p == 1023) {
        for (int q = threadIdx.x; q < N; q += 256) row[q] = (q == 1023) ? 1.0f : 0.0f;
        return;
    }
    __shared__ float sm[256];
    float s = 0.0f;
    for (int q = threadIdx.x; q < 1023; q += 256) s += row[q];   // sum of (1e-7 - WP)
    sm[threadIdx.x] = s;
    __syncthreads();
    for (int st = 128; st > 0; st >>= 1) {
        if (threadIdx.x < st) sm[threadIdx.x] += sm[threadIdx.x + st];
        __syncthreads();
    }
    if (threadIdx.x == 0) {
        float wpsum = 1023.0f * 1e-7f - sm[0] + g_col0[b * N + (p + 1)];
        row[p] = wpsum + 1e-7f;
        row[1023] = 0.0f;
    }
}

// ---------------- blocked unpivoted LU (nb = 64) ----------------------------

// 256 threads; no integer division in the hot loop.
__global__ void k_panelLU(int k) {
    int mat = blockIdx.x;
    float* A = g_LU + (size_t)mat * N * N;
    __shared__ float sA[64][65];
    int tid = threadIdx.x;               // 256
    int cc = tid & 63;                   // column for rank-1 update
    int rg = tid >> 6;                   // row group 0..3
    for (int t = tid; t < 64 * 64; t += 256) {
        int r = t >> 6, c = t & 63;
        sA[r][c] = A[(size_t)(k + r) * N + k + c];
    }
    __syncthreads();
    #pragma unroll 1
    for (int c = 0; c < 64; c++) {
        if (tid >= c && tid < 64) {
            float inv = 1.0f / sA[c][c];
            if (tid == c) g_invd[mat * 64 + c] = inv;
            else sA[tid][c] *= inv;
        }
        __syncthreads();
        if (cc > c) {
            float ucc = sA[c][cc];
            #pragma unroll 1
            for (int r = c + 1 + rg; r < 64; r += 4)
                sA[r][cc] -= sA[r][c] * ucc;
        }
        __syncthreads();
    }
    for (int t = tid; t < 64 * 64; t += 256) {
        int r = t >> 6, c = t & 63;
        A[(size_t)(k + r) * N + k + c] = sA[r][c];
    }
}

// fused TRSMs, 256 threads: z==0 -> L21 = A21*U11^{-1}; z==1 -> U12 = L11^{-1}*A12
__global__ void k_trsm(int k) {
    int mat = blockIdx.y;
    float* A = g_LU + (size_t)mat * N * N;
    int tid = threadIdx.x;  // 256
    __shared__ float sU[64][65];
    __shared__ float sInv[64];
    for (int t = tid; t < 64 * 64; t += 256) {
        int r = t >> 6, c = t & 63;
        sU[r][c] = A[(size_t)(k + r) * N + k + c];
    }
    if (blockIdx.z == 0 && tid < 64) sInv[tid] = g_invd[mat * 64 + tid];
    __syncthreads();
    int g = k + 64 + blockIdx.x * 256 + tid;
    if (g >= N) return;
    if (blockIdx.z == 0) {
        float* rowp = A + (size_t)g * N + k;
        float a[64];
        #pragma unroll
        for (int c = 0; c < 16; c++) {
            float4 v = reinterpret_cast<const float4*>(rowp)[c];
            a[4 * c] = v.x; a[4 * c + 1] = v.y; a[4 * c + 2] = v.z; a[4 * c + 3] = v.w;
        }
        #pragma unroll
        for (int d = 0; d < 64; d++) {
            a[d] *= sInv[d];
            #pragma unroll
            for (int c = d + 1; c < 64; c++) a[c] -= a[d] * sU[d][c];
        }
        #pragma unroll
        for (int c = 0; c < 16; c++) {
            float4 v; v.x = a[4 * c]; v.y = a[4 * c + 1]; v.z = a[4 * c + 2]; v.w = a[4 * c + 3];
            reinterpret_cast<float4*>(rowp)[c] = v;
        }
    } else {
        float a[64];
        #pragma unroll
        for (int d = 0; d < 64; d++) a[d] = A[(size_t)(k + d) * N + g];
        #pragma unroll
        for (int d = 0; d < 64; d++) {
            #pragma unroll
            for (int r = d + 1; r < 64; r++) a[r] -= sU[r][d] * a[d];
        }
        #pragma unroll
        for (int d = 0; d < 64; d++) A[(size_t)(k + d) * N + g] = a[d];
    }
}

// trailing update: C -= L21 * U12; 128x128 tile, 8x8 micro, double-buffered.
__global__ void __launch_bounds__(256, 2) k_gemm(int k) {
    int mat = blockIdx.z;
    float* M = g_LU + (size_t)mat * N * N;
    int row0 = k + 64 + blockIdx.y * 128;
    int col0 = k + 64 + blockIdx.x * 128;

    __shared__ float sA[2][8][132];   // sA[buf][kk][row]
    __shared__ float sB[2][8][128];   // sB[buf][kk][col]

    int tid = threadIdx.x;            // 256
    int tx = tid & 15, ty = tid >> 4;

    // A load mapping: row = tid>>1 (0..127), col-quad = (tid&1)*4
    int a_row = tid >> 1;
    int a_c4  = (tid & 1) * 4;
    int a_grow = min(row0 + a_row, N - 1);
    // B load mapping: row = tid>>5 (0..7), col-quad = (tid&31)*4
    int b_row = tid >> 5;
    int b_c4  = (tid & 31) * 4;
    int b_gcol = min(col0 + b_c4, N - 4);

    float acc[8][8];
    #pragma unroll
    for (int y = 0; y < 8; y++)
        #pragma unroll
        for (int xq = 0; xq < 8; xq++) acc[y][xq] = 0.0f;

    // prologue: load chunk 0
    float4 av = *reinterpret_cast<const float4*>(&M[(size_t)a_grow * N + k + a_c4]);
    float4 bv = *reinterpret_cast<const float4*>(&M[(size_t)(k + b_row) * N + b_gcol]);
    sA[0][a_c4 + 0][a_row] = av.x; sA[0][a_c4 + 1][a_row] = av.y;
    sA[0][a_c4 + 2][a_row] = av.z; sA[0][a_c4 + 3][a_row] = av.w;
    *reinterpret_cast<float4*>(&sB[0][b_row][b_c4]) = bv;
    __syncthreads();

    int p = 0;
    #pragma unroll 1
    for (int kk = 8; kk < 64; kk += 8) {
        float4 av2 = *reinterpret_cast<const float4*>(&M[(size_t)a_grow * N + k + kk + a_c4]);
        float4 bv2 = *reinterpret_cast<const float4*>(&M[(size_t)(k + kk + b_row) * N + b_gcol]);
        #pragma unroll
        for (int t = 0; t < 8; t++) {
            float4 alo = *reinterpret_cast<const float4*>(&sA[p][t][ty * 4]);
            float4 ahi = *reinterpret_cast<const float4*>(&sA[p][t][64 + ty * 4]);
            float4 blo = *reinterpret_cast<const float4*>(&sB[p][t][tx * 4]);
            float4 bhi = *reinterpret_cast<const float4*>(&sB[p][t][64 + tx * 4]);
            float ar[8] = {alo.x, alo.y, alo.z, alo.w, ahi.x, ahi.y, ahi.z, ahi.w};
            float br[8] = {blo.x, blo.y, blo.z, blo.w, bhi.x, bhi.y, bhi.z, bhi.w};
            #pragma unroll
            for (int y = 0; y < 8; y++)
                #pragma unroll
                for (int xq = 0; xq < 8; xq++)
                    acc[y][xq] += ar[y] * br[xq];
        }
        int q = 1 - p;
        sA[q][a_c4 + 0][a_row] = av2.x; sA[q][a_c4 + 1][a_row] = av2.y;
        sA[q][a_c4 + 2][a_row] = av2.z; sA[q][a_c4 + 3][a_row] = av2.w;
        *reinterpret_cast<float4*>(&sB[q][b_row][b_c4]) = bv2;
        __syncthreads();
        p = q;
    }
    #pragma unroll
    for (int t = 0; t < 8; t++) {
        float4 alo = *reinterpret_cast<const float4*>(&sA[p][t][ty * 4]);
        float4 ahi = *reinterpret_cast<const float4*>(&sA[p][t][64 + ty * 4]);
        float4 blo = *reinterpret_cast<const float4*>(&sB[p][t][tx * 4]);
        float4 bhi = *reinterpret_cast<const float4*>(&sB[p][t][64 + tx * 4]);
        float ar[8] = {alo.x, alo.y, alo.z, alo.w, ahi.x, ahi.y, ahi.z, ahi.w};
        float br[8] = {blo.x, blo.y, blo.z, blo.w, bhi.x, bhi.y, bhi.z, bhi.w};
        #pragma unroll
        for (int y = 0; y < 8; y++)
            #pragma unroll
            for (int xq = 0; xq < 8; xq++)
                acc[y][xq] += ar[y] * br[xq];
    }

    // store: rows {row0+ty*4+i, row0+64+ty*4+i}, cols {col0+tx*4.., col0+64+tx*4..}
    #pragma unroll
    for (int h = 0; h < 2; h++) {
        #pragma unroll
        for (int iy = 0; iy < 4; iy++) {
            int r = row0 + h * 64 + ty * 4 + iy;
            if (r < N) {
                int yidx = h * 4 + iy;
                int c_lo = col0 + tx * 4;
                if (c_lo < N) {
                    float4* cp = reinterpret_cast<float4*>(&M[(size_t)r * N + c_lo]);
                    float4 cv = *cp;
                    cv.x -= acc[yidx][0]; cv.y -= acc[yidx][1];
                    cv.z -= acc[yidx][2]; cv.w -= acc[yidx][3];
                    *cp = cv;
                }
                int c_hi = col0 + 64 + tx * 4;
                if (c_hi < N) {
                    float4* cp = reinterpret_cast<float4*>(&M[(size_t)r * N + c_hi]);
                    float4 cv = *cp;
                    cv.x -= acc[yidx][4]; cv.y -= acc[yidx][5];
                    cv.z -= acc[yidx][6]; cv.w -= acc[yidx][7];
                    *cp = cv;
                }
            }
        }
    }
}

// ---------------- epilogue ---------------------------------------------------

__global__ void k_logdet() {
    int mat = blockIdx.x;
    __shared__ float sm[256];
    float s = 0.0f;
    for (int d = threadIdx.x; d < 1023; d += 256)
        s += logf(fabsf(g_LU[(size_t)mat * N * N + (size_t)d * N + d]));
    sm[threadIdx.x] = s;
    __syncthreads();
    for (int st = 128; st > 0; st >>= 1) {
        if (threadIdx.x < st) sm[threadIdx.x] += sm[threadIdx.x + st];
        __syncthreads();
    }
    if (threadIdx.x == 0) g_ld[mat] = sm[0];
}

__global__ void k_out(float* __restrict__ out) {
    int b = threadIdx.x;
    if (b < BATCH) out[b] = g_y[b] + g_ld[b] - g_ld[32];
}

// ---------------- launch ------------------------------------------------------
extern "C" void kernel_launch(void* const* d_in, const int* in_sizes, int n_in,
                              void* d_out, int out_size) {
    const int*   x  = (const int*)d_in[0];
    const float* W  = (const float*)d_in[1];
    const float* Vc = (const float*)d_in[2];
    const float* Ec = (const float*)d_in[3];
    float* out = (float*)d_out;
    (void)in_sizes; (void)n_in; (void)out_size;

    k_vsoftmax<<<4, 256>>>(Vc);
    k_pr<<<BATCH, 1024>>>(x);
    k_ws<<<N, 256>>>(W);
    k_sink<<<dim3(8, N - 1), 128>>>(x, Ec);
    k_fin<<<dim3(N, BATCH), 256>>>();

    for (int s = 0; s < 16; s++) {
        int k = s * 64;
        k_panelLU<<<NMAT, 256>>>(k);
        int m2 = N - k - 64;
        if (m2 > 0) {
            int gtr = (m2 + 255) / 256;
            int gx  = (m2 + 127) / 128;
            k_trsm<<<dim3(gtr, NMAT, 2), 256>>>(k);
            k_gemm<<<dim3(gx, gx, NMAT), 256>>>(k);
        }
    }

    k_logdet<<<NMAT, 256>>>();
    k_out<<<1, 32>>>(out);
}